// round 14
// baseline (speedup 1.0000x reference)
#include <cuda_runtime.h>
#include <cuda_fp16.h>
#include <cuda_bf16.h>

#define N_NODES 50000
#define E_EDGES 800000
#define D_INP   128
#define D_HID   256
#define SCAN_BLOCKS ((N_NODES + 1023) / 1024)   // 49

// ---------------- scratch (device globals; no allocation allowed) ----------------
__device__ __align__(256) __half g_aggX[(size_t)N_NODES * D_INP];   // aggregated x (fp16)
__device__ __align__(256) __half g_h   [(size_t)N_NODES * D_HID];   // ch0 hidden (fp16)
__device__ __align__(256) __half g_agg [(size_t)N_NODES * D_HID];   // ch0 aggregated (fp16)
__device__ __align__(256) __half g_h2  [(size_t)N_NODES * D_HID];   // ch1 hidden (fp16)
__device__ __align__(256) __half g_agg2[(size_t)N_NODES * D_HID];   // ch1 aggregated (fp16)
__device__ __align__(256) int2   g_cw  [E_EDGES];                   // CSR {src, w-bits}
__device__ int   g_cnt[N_NODES];
__device__ int   g_rowptr[N_NODES + 1];
__device__ int   g_pos[N_NODES];
__device__ float g_dinv[N_NODES];
__device__ int   g_blksum[SCAN_BLOCKS];
__device__ int   g_blkoff[SCAN_BLOCKS];
__device__ int   g_mode32;     // 1 = indices are int32, 0 = int64 (read low words)

__device__ __forceinline__ int idx_at(const int* __restrict__ p32, int mode32, int idx) {
    return mode32 ? p32[idx] : p32[2 * (size_t)idx];
}

__device__ __forceinline__ unsigned f2tf(float f) {
    unsigned u;
    asm("cvt.rna.tf32.f32 %0, %1;" : "=r"(u) : "f"(f));
    return u;
}

// ---------------- init: zero counts + dtype detection (block 0) ----------------
__global__ void init_kernel(const int* __restrict__ e32) {
    int i = blockIdx.x * blockDim.x + threadIdx.x;
    if (i < N_NODES) g_cnt[i] = 0;
    if (blockIdx.x == 0) {
        __shared__ int any;
        if (threadIdx.x == 0) any = 0;
        __syncthreads();
        int a = 0;
        #pragma unroll
        for (int s = 0; s < 4; s++) {
            int idx = threadIdx.x * 4 + s;           // 0..1023 samples
            a |= e32[2 * (idx * 391) + 1];           // odd words, within first E ints
        }
        if (a != 0) atomicOr(&any, 1);
        __syncthreads();
        if (threadIdx.x == 0) g_mode32 = any;
    }
}

__global__ void count_kernel(const int* __restrict__ e32) {
    int e = blockIdx.x * blockDim.x + threadIdx.x;
    if (e < E_EDGES) {
        int d = idx_at(e32, g_mode32, E_EDGES + e);
        atomicAdd(&g_cnt[d], 1);
    }
}

// ---------------- hierarchical scan ----------------
__global__ void scanA_kernel() {        // grid=SCAN_BLOCKS, block=1024
    __shared__ int wsum[32];
    int t = threadIdx.x, lane = t & 31, w = t >> 5;
    int idx = blockIdx.x * 1024 + t;
    int v = (idx < N_NODES) ? g_cnt[idx] : 0;
    if (idx < N_NODES) g_dinv[idx] = rsqrtf((float)(v + 1));   // +1 self-loop
    int inc = v;
    #pragma unroll
    for (int d = 1; d < 32; d <<= 1) {
        int n = __shfl_up_sync(0xffffffffu, inc, d);
        if (lane >= d) inc += n;
    }
    if (lane == 31) wsum[w] = inc;
    __syncthreads();
    if (w == 0) {
        int s = wsum[lane];
        #pragma unroll
        for (int d = 1; d < 32; d <<= 1) {
            int n = __shfl_up_sync(0xffffffffu, s, d);
            if (lane >= d) s += n;
        }
        wsum[lane] = s;
    }
    __syncthreads();
    int wbase = (w == 0) ? 0 : wsum[w - 1];
    if (idx < N_NODES) g_rowptr[idx] = wbase + inc - v;   // block-local exclusive
    if (t == 1023) g_blksum[blockIdx.x] = wbase + inc;
}

__global__ void scanB_kernel() {        // 1 block, 64 threads
    int t = threadIdx.x;
    int v = (t < SCAN_BLOCKS) ? g_blksum[t] : 0;
    __shared__ int sh[64];
    sh[t] = v;
    __syncthreads();
    #pragma unroll
    for (int d = 1; d < 64; d <<= 1) {
        int add = (t >= d) ? sh[t - d] : 0;
        __syncthreads();
        sh[t] += add;
        __syncthreads();
    }
    if (t < SCAN_BLOCKS) g_blkoff[t] = sh[t] - v;         // exclusive
    if (t == 0) g_rowptr[N_NODES] = sh[SCAN_BLOCKS - 1];
}

__global__ void scanC_kernel() {
    int i = blockIdx.x * blockDim.x + threadIdx.x;
    if (i < N_NODES) {
        int r = g_rowptr[i] + g_blkoff[i >> 10];
        g_rowptr[i] = r;
        g_pos[i]    = r;
    }
}

__global__ void fill_kernel(const int* __restrict__ e32) {
    int e = blockIdx.x * blockDim.x + threadIdx.x;
    if (e < E_EDGES) {
        int m = g_mode32;
        int s = idx_at(e32, m, e);
        int d = idx_at(e32, m, E_EDGES + e);
        int p = atomicAdd(&g_pos[d], 1);
        g_cw[p] = make_int2(s, __float_as_int(g_dinv[s] * g_dinv[d]));
    }
}

// ---------------- layer-0 aggregation of x (fp32 in, fp16 out): 8 nodes/256-thread blk ----
template <int D>
__global__ void aggregate_kernel(const float* __restrict__ h, __half* __restrict__ out) {
    const int TPN = D / 4;                     // threads per node (float4 each)
    const int NPB = 256 / TPN;                 // nodes per block
    int v = blockIdx.x * NPB + threadIdx.x / TPN;
    int t = threadIdx.x % TPN;
    if (v >= N_NODES) return;
    const float4* h4 = (const float4*)h;
    float dv = g_dinv[v];
    float sw = dv * dv;
    float4 hv = h4[(size_t)v * TPN + t];
    float4 acc = make_float4(sw * hv.x, sw * hv.y, sw * hv.z, sw * hv.w);
    int beg = g_rowptr[v];
    int end = g_rowptr[v + 1];
    int j = beg;
    for (; j + 8 <= end; j += 8) {            // 8 gathers in flight
        int2 cw[8];
        #pragma unroll
        for (int u = 0; u < 8; u++) cw[u] = __ldg(&g_cw[j + u]);
        float4 hh[8];
        #pragma unroll
        for (int u = 0; u < 8; u++) hh[u] = h4[(size_t)cw[u].x * TPN + t];
        #pragma unroll
        for (int u = 0; u < 8; u++) {
            float wj = __int_as_float(cw[u].y);
            acc.x += wj * hh[u].x;
            acc.y += wj * hh[u].y;
            acc.z += wj * hh[u].z;
            acc.w += wj * hh[u].w;
        }
    }
    for (; j < end; ++j) {
        int2 cw = __ldg(&g_cw[j]);
        float wj = __int_as_float(cw.y);
        float4 hc = h4[(size_t)cw.x * TPN + t];
        acc.x += wj * hc.x;
        acc.y += wj * hc.y;
        acc.z += wj * hc.z;
        acc.w += wj * hc.w;
    }
    __half2 p0 = __floats2half2_rn(acc.x, acc.y);
    __half2 p1 = __floats2half2_rn(acc.z, acc.w);
    uint2 o = make_uint2(*(unsigned*)&p0, *(unsigned*)&p1);
    ((uint2*)out)[(size_t)v * TPN + t] = o;
}

// ---------------- fp16-in/fp16-out aggregation (D=256): 32 threads/node ----------------
__device__ __forceinline__ void h8_to_f8(const uint4& u, float* f) {
    float2 a = __half22float2(*(const __half2*)&u.x);
    float2 b = __half22float2(*(const __half2*)&u.y);
    float2 c = __half22float2(*(const __half2*)&u.z);
    float2 d = __half22float2(*(const __half2*)&u.w);
    f[0] = a.x; f[1] = a.y; f[2] = b.x; f[3] = b.y;
    f[4] = c.x; f[5] = c.y; f[6] = d.x; f[7] = d.y;
}

__global__ void aggregate_h(const __half* __restrict__ h, __half* __restrict__ out) {
    int v = blockIdx.x * 8 + (threadIdx.x >> 5);   // 8 nodes per 256-thread block
    int t = threadIdx.x & 31;                      // 32 threads per node
    if (v >= N_NODES) return;
    const uint4* h4 = (const uint4*)h;             // 16B = 8 halves
    float dv = g_dinv[v];
    float sw = dv * dv;
    float acc[8], f[8];
    uint4 hv = h4[(size_t)v * 32 + t];
    h8_to_f8(hv, f);
    #pragma unroll
    for (int k = 0; k < 8; k++) acc[k] = sw * f[k];
    int beg = g_rowptr[v];
    int end = g_rowptr[v + 1];
    int j = beg;
    for (; j + 8 <= end; j += 8) {                 // 8 gathers in flight
        int2 cw[8];
        #pragma unroll
        for (int u = 0; u < 8; u++) cw[u] = __ldg(&g_cw[j + u]);
        uint4 hh[8];
        #pragma unroll
        for (int u = 0; u < 8; u++) hh[u] = h4[(size_t)cw[u].x * 32 + t];
        #pragma unroll
        for (int u = 0; u < 8; u++) {
            float wj = __int_as_float(cw[u].y);
            h8_to_f8(hh[u], f);
            #pragma unroll
            for (int k = 0; k < 8; k++) acc[k] += wj * f[k];
        }
    }
    for (; j < end; ++j) {
        int2 cw = __ldg(&g_cw[j]);
        float wj = __int_as_float(cw.y);
        uint4 hc = h4[(size_t)cw.x * 32 + t];
        h8_to_f8(hc, f);
        #pragma unroll
        for (int k = 0; k < 8; k++) acc[k] += wj * f[k];
    }
    __half2 p0 = __floats2half2_rn(acc[0], acc[1]);
    __half2 p1 = __floats2half2_rn(acc[2], acc[3]);
    __half2 p2 = __floats2half2_rn(acc[4], acc[5]);
    __half2 p3 = __floats2half2_rn(acc[6], acc[7]);
    uint4 o = make_uint4(*(unsigned*)&p0, *(unsigned*)&p1,
                         *(unsigned*)&p2, *(unsigned*)&p3);
    ((uint4*)out)[(size_t)v * 32 + t] = o;
}

// ---------------- tf32 GEMM: fp16 A, fp32 W, fp16 C output ----------------
// C[N,256] = A[N,K] @ W[K,256]; BM=128 BN=128 BK=32, 8 warps (R8-proven body)
template <int K>
__launch_bounds__(256)
__global__ void gemm_tf32(const __half* __restrict__ A, const float* __restrict__ W,
                          const float* __restrict__ bias, __half* __restrict__ C) {
    __shared__ __align__(16) unsigned As[8 * 128 * 4];   // [chunk][row^chunk][k%4]
    __shared__ __align__(16) unsigned Bs[32 * 136];      // [k][n] stride 136

    const int tid  = threadIdx.x;
    const int lane = tid & 31, wid = tid >> 5;
    const int g  = lane >> 2, t4 = lane & 3;
    const int m0 = blockIdx.x * 128, n0 = blockIdx.y * 128;
    const int wr = (wid & 3) * 32;
    const int wc = (wid >> 2) * 64;

    float acc[2][8][4];
    #pragma unroll
    for (int mt = 0; mt < 2; mt++)
        #pragma unroll
        for (int nt = 0; nt < 8; nt++)
            #pragma unroll
            for (int r = 0; r < 4; r++) acc[mt][nt][r] = 0.f;

    const int la_row = tid >> 3;
    const int la_ch  = tid & 7;
    const int lb_k   = tid >> 5;
    const int lb_n   = (tid & 31) * 4;

    uint2 aR[4];
    float4 bR[4];
    auto fetch = [&](int k0) {
        #pragma unroll
        for (int i = 0; i < 4; i++) {
            int m = m0 + la_row + i * 32;
            aR[i] = (m < N_NODES)
                  ? *(const uint2*)&A[(size_t)m * K + k0 + la_ch * 4]
                  : make_uint2(0u, 0u);
        }
        #pragma unroll
        for (int i = 0; i < 4; i++) {
            int k = k0 + lb_k + i * 8;
            bR[i] = *(const float4*)&W[(size_t)k * 256 + n0 + lb_n];
        }
    };

    fetch(0);
    for (int k0 = 0; k0 < K; k0 += 32) {
        #pragma unroll
        for (int i = 0; i < 4; i++) {
            float2 lo = __half22float2(*(const __half2*)&aR[i].x);
            float2 hi = __half22float2(*(const __half2*)&aR[i].y);
            uint4 v = make_uint4(f2tf(lo.x), f2tf(lo.y), f2tf(hi.x), f2tf(hi.y));
            int row = la_row + i * 32;
            *(uint4*)&As[(la_ch * 128 + (row ^ la_ch)) * 4] = v;
        }
        #pragma unroll
        for (int i = 0; i < 4; i++) {
            uint4 v = make_uint4(f2tf(bR[i].x), f2tf(bR[i].y), f2tf(bR[i].z), f2tf(bR[i].w));
            *(uint4*)&Bs[(lb_k + i * 8) * 136 + lb_n] = v;
        }
        __syncthreads();
        if (k0 + 32 < K) fetch(k0 + 32);

        #pragma unroll
        for (int kk = 0; kk < 4; kk++) {
            const int c0 = 2 * kk, c1 = 2 * kk + 1;
            unsigned a[2][4];
            #pragma unroll
            for (int mt = 0; mt < 2; mt++) {
                int m = wr + mt * 16 + g;
                a[mt][0] = As[(c0 * 128 + (m ^ c0)) * 4 + t4];
                a[mt][1] = As[(c0 * 128 + ((m + 8) ^ c0)) * 4 + t4];
                a[mt][2] = As[(c1 * 128 + (m ^ c1)) * 4 + t4];
                a[mt][3] = As[(c1 * 128 + ((m + 8) ^ c1)) * 4 + t4];
            }
            #pragma unroll
            for (int nt = 0; nt < 8; nt++) {
                int n = wc + nt * 8 + g;
                unsigned b0 = Bs[(kk * 8 + t4) * 136 + n];
                unsigned b1 = Bs[(kk * 8 + t4 + 4) * 136 + n];
                #pragma unroll
                for (int mt = 0; mt < 2; mt++) {
                    asm volatile(
                        "mma.sync.aligned.m16n8k8.row.col.f32.tf32.tf32.f32 "
                        "{%0,%1,%2,%3}, {%4,%5,%6,%7}, {%8,%9}, {%0,%1,%2,%3};"
                        : "+f"(acc[mt][nt][0]), "+f"(acc[mt][nt][1]),
                          "+f"(acc[mt][nt][2]), "+f"(acc[mt][nt][3])
                        : "r"(a[mt][0]), "r"(a[mt][1]), "r"(a[mt][2]), "r"(a[mt][3]),
                          "r"(b0), "r"(b1));
                }
            }
        }
        __syncthreads();
    }

    #pragma unroll
    for (int mt = 0; mt < 2; mt++) {
        int r0 = m0 + wr + mt * 16 + g;
        #pragma unroll
        for (int nt = 0; nt < 8; nt++) {
            int n = n0 + wc + nt * 8 + 2 * t4;
            float bA = bias[n], bB = bias[n + 1];
            if (r0 < N_NODES) {
                float tx = acc[mt][nt][0] + bA;
                float ty = acc[mt][nt][1] + bB;
                *(__half2*)&C[(size_t)r0 * 256 + n] =
                    __floats2half2_rn(fmaxf(tx, 0.f) + tx, fmaxf(ty, 0.f) + ty);
            }
            int r1 = r0 + 8;
            if (r1 < N_NODES) {
                float tx = acc[mt][nt][2] + bA;
                float ty = acc[mt][nt][3] + bB;
                *(__half2*)&C[(size_t)r1 * 256 + n] =
                    __floats2half2_rn(fmaxf(tx, 0.f) + tx, fmaxf(ty, 0.f) + ty);
            }
        }
    }
}

// ---------------- last-layer GEMM with fused LayerNorm (BM=64, BN=256, K=256) ----------
#define GL_AS_WORDS (64 * 64 * 4)
#define GL_BS_WORDS (16 * 260)
#define GL_SMEM_BYTES ((GL_AS_WORDS + GL_BS_WORDS) * 4)

__launch_bounds__(256, 2)
__global__ void gemm_ln(const __half* __restrict__ A, const float* __restrict__ W,
                        const float* __restrict__ bias,
                        const float* __restrict__ lnw, const float* __restrict__ lnb,
                        float* __restrict__ C) {
    extern __shared__ __align__(16) unsigned smem[];
    unsigned* As = smem;                       // [row(64)][chunk ^ (row&7)(64)][4]
    unsigned* Bs = smem + GL_AS_WORDS;         // [k(16)][n] stride 260
    float*    Sln = (float*)smem;              // LN scratch (reuses As region, 64KB)

    const int tid  = threadIdx.x;
    const int lane = tid & 31, wid = tid >> 5;
    const int g = lane >> 2, t4 = lane & 3;
    const int m0 = blockIdx.x * 64;
    const int wr = (wid >> 2) * 32;            // 2 row groups
    const int wc = (wid & 3) * 64;             // 4 col groups

    // ---- stage A: load 64x256 fp16 A tile into swizzled tf32 SMEM ----
    #pragma unroll
    for (int it = 0; it < 16; ++it) {
        int idx = it * 256 + tid;
        int row = idx >> 6;                    // 0..63
        int ch  = idx & 63;                    // k/4 chunk
        int m = m0 + row;
        uint2 av = (m < N_NODES)
                 ? *(const uint2*)&A[(size_t)m * 256 + ch * 4]
                 : make_uint2(0u, 0u);
        float2 lo = __half22float2(*(const __half2*)&av.x);
        float2 hi = __half22float2(*(const __half2*)&av.y);
        uint4 tv = make_uint4(f2tf(lo.x), f2tf(lo.y), f2tf(hi.x), f2tf(hi.y));
        *(uint4*)&As[(row * 64 + (ch ^ (row & 7))) * 4] = tv;
    }
    __syncthreads();

    // ---- stage B: GEMM over K=256 in 16-k slabs ----
    float acc[2][8][4];
    #pragma unroll
    for (int mt = 0; mt < 2; mt++)
        #pragma unroll
        for (int nt = 0; nt < 8; nt++)
            #pragma unroll
            for (int r = 0; r < 4; r++) acc[mt][nt][r] = 0.f;

    const int lb_k = tid >> 6;                 // 0..3 (+i*4 -> rows 0..15)
    const int lb_n = (tid & 63) * 4;           // full 256 cols
    float4 bR[4];
    auto fetchW = [&](int k0) {
        #pragma unroll
        for (int i = 0; i < 4; i++)
            bR[i] = *(const float4*)&W[(size_t)(k0 + lb_k + i * 4) * 256 + lb_n];
    };

    fetchW(0);
    for (int k0 = 0; k0 < 256; k0 += 16) {
        #pragma unroll
        for (int i = 0; i < 4; i++) {
            uint4 v = make_uint4(f2tf(bR[i].x), f2tf(bR[i].y), f2tf(bR[i].z), f2tf(bR[i].w));
            *(uint4*)&Bs[(lb_k + i * 4) * 260 + lb_n] = v;
        }
        __syncthreads();
        if (k0 + 16 < 256) fetchW(k0 + 16);

        const int cb = k0 >> 2;
        #pragma unroll
        for (int kk = 0; kk < 2; kk++) {
            const int c0 = cb + 2 * kk, c1 = c0 + 1;
            unsigned a[2][4];
            #pragma unroll
            for (int mt = 0; mt < 2; mt++) {
                int m = wr + mt * 16 + g;      // m&7 == g
                a[mt][0] = As[(m * 64 + (c0 ^ g)) * 4 + t4];
                a[mt][1] = As[((m + 8) * 64 + (c0 ^ g)) * 4 + t4];
                a[mt][2] = As[(m * 64 + (c1 ^ g)) * 4 + t4];
                a[mt][3] = As[((m + 8) * 64 + (c1 ^ g)) * 4 + t4];
            }
            #pragma unroll
            for (int nt = 0; nt < 8; nt++) {
                int n = wc + nt * 8 + g;
                unsigned b0 = Bs[(kk * 8 + t4) * 260 + n];
                unsigned b1 = Bs[(kk * 8 + t4 + 4) * 260 + n];
                #pragma unroll
                for (int mt = 0; mt < 2; mt++) {
                    asm volatile(
                        "mma.sync.aligned.m16n8k8.row.col.f32.tf32.tf32.f32 "
                        "{%0,%1,%2,%3}, {%4,%5,%6,%7}, {%8,%9}, {%0,%1,%2,%3};"
                        : "+f"(acc[mt][nt][0]), "+f"(acc[mt][nt][1]),
                          "+f"(acc[mt][nt][2]), "+f"(acc[mt][nt][3])
                        : "r"(a[mt][0]), "r"(a[mt][1]), "r"(a[mt][2]), "r"(a[mt][3]),
                          "r"(b0), "r"(b1));
                }
            }
        }
        __syncthreads();
    }

    // ---- stage C: bias + relu-residual -> Sln, then LayerNorm -> C ----
    #pragma unroll
    for (int mt = 0; mt < 2; mt++) {
        int lr = wr + mt * 16 + g;
        #pragma unroll
        for (int nt = 0; nt < 8; nt++) {
            int n = wc + nt * 8 + 2 * t4;
            float bA = bias[n], bB = bias[n + 1];
            float tx = acc[mt][nt][0] + bA;
            float ty = acc[mt][nt][1] + bB;
            *(float2*)&Sln[lr * 256 + n] =
                make_float2(fmaxf(tx, 0.f) + tx, fmaxf(ty, 0.f) + ty);
            tx = acc[mt][nt][2] + bA;
            ty = acc[mt][nt][3] + bB;
            *(float2*)&Sln[(lr + 8) * 256 + n] =
                make_float2(fmaxf(tx, 0.f) + tx, fmaxf(ty, 0.f) + ty);
        }
    }
    __syncthreads();
    const float4* lnw4 = (const float4*)lnw;
    const float4* lnb4 = (const float4*)lnb;
    #pragma unroll 1
    for (int r = 0; r < 8; r++) {
        int row = wid * 8 + r;
        int v = m0 + row;
        if (v >= N_NODES) break;
        float4 a = ((const float4*)&Sln[row * 256])[lane];
        float4 b = ((const float4*)&Sln[row * 256])[lane + 32];
        float s1 = a.x + a.y + a.z + a.w + b.x + b.y + b.z + b.w;
        float s2 = a.x*a.x + a.y*a.y + a.z*a.z + a.w*a.w
                 + b.x*b.x + b.y*b.y + b.z*b.z + b.w*b.w;
        #pragma unroll
        for (int off = 16; off > 0; off >>= 1) {
            s1 += __shfl_xor_sync(0xffffffffu, s1, off);
            s2 += __shfl_xor_sync(0xffffffffu, s2, off);
        }
        float mean = s1 * (1.f / 256.f);
        float var  = s2 * (1.f / 256.f) - mean * mean;
        float rs = rsqrtf(var + 1e-6f);
        float4 w1 = lnw4[lane], w2 = lnw4[lane + 32];
        float4 z1 = lnb4[lane], z2 = lnb4[lane + 32];
        float4 o1 = make_float4((a.x - mean) * rs * w1.x + z1.x,
                                (a.y - mean) * rs * w1.y + z1.y,
                                (a.z - mean) * rs * w1.z + z1.z,
                                (a.w - mean) * rs * w1.w + z1.w);
        float4 o2 = make_float4((b.x - mean) * rs * w2.x + z2.x,
                                (b.y - mean) * rs * w2.y + z2.y,
                                (b.z - mean) * rs * w2.z + z2.z,
                                (b.w - mean) * rs * w2.w + z2.w);
        ((float4*)&C[(size_t)v * 256])[lane]      = o1;
        ((float4*)&C[(size_t)v * 256])[lane + 32] = o2;
    }
}

__global__ void batchs_kernel(const int* __restrict__ b32, float* __restrict__ out) {
    int i = blockIdx.x * blockDim.x + threadIdx.x;
    if (i < N_NODES) {
        float bv = (float)idx_at(b32, g_mode32, i);
        out[i]           = bv;   // channel 0
        out[N_NODES + i] = bv;   // channel 1
    }
}

// ---------------- launcher (R8-proven schedule: batchs hoist + lockstep fork) ----------
extern "C" void kernel_launch(void* const* d_in, const int* in_sizes, int n_in,
                              void* d_out, int out_size) {
    const float* x    = (const float*)d_in[0];
    const int*   e32  = (const int*)d_in[1];
    const int*   b32  = (const int*)d_in[2];
    const float* W0 = (const float*)d_in[3];
    const float* b0 = (const float*)d_in[4];
    const float* W1 = (const float*)d_in[5];
    const float* b1 = (const float*)d_in[6];
    const float* W2 = (const float*)d_in[7];
    const float* b2 = (const float*)d_in[8];
    const float* lnw = (const float*)d_in[9];
    const float* lnb = (const float*)d_in[10];
    float* out = (float*)d_out;

    __half *p_aggX, *p_h, *p_agg, *p_h2, *p_agg2;
    cudaGetSymbolAddress((void**)&p_aggX, g_aggX);
    cudaGetSymbolAddress((void**)&p_h,    g_h);
    cudaGetSymbolAddress((void**)&p_agg,  g_agg);
    cudaGetSymbolAddress((void**)&p_h2,   g_h2);
    cudaGetSymbolAddress((void**)&p_agg2, g_agg2);

    static cudaStream_t s2 = nullptr;
    static cudaEvent_t evI = nullptr, evF = nullptr, evJ = nullptr;
    if (!s2) {
        cudaStreamCreateWithFlags(&s2, cudaStreamNonBlocking);
        cudaEventCreateWithFlags(&evI, cudaEventDisableTiming);
        cudaEventCreateWithFlags(&evF, cudaEventDisableTiming);
        cudaEventCreateWithFlags(&evJ, cudaEventDisableTiming);
        cudaFuncSetAttribute(gemm_ln,
                             cudaFuncAttributeMaxDynamicSharedMemorySize, GL_SMEM_BYTES);
    }

    const int TB = 256;
    init_kernel <<<(N_NODES + TB - 1) / TB, TB>>>(e32);
    cudaEventRecord(evI, 0);                    // g_mode32 ready
    cudaStreamWaitEvent(s2, evI, 0);
    batchs_kernel<<<(N_NODES + TB - 1) / TB, TB, 0, s2>>>(b32, out + (size_t)2 * N_NODES * 256);

    count_kernel<<<(E_EDGES + TB - 1) / TB, TB>>>(e32);
    scanA_kernel<<<SCAN_BLOCKS, 1024>>>();
    scanB_kernel<<<1, 64>>>();
    scanC_kernel<<<(N_NODES + TB - 1) / TB, TB>>>();
    fill_kernel <<<(E_EDGES + TB - 1) / TB, TB>>>(e32);

    // shared layer-0 aggregation of x (fp32 in, fp16 out)
    aggregate_kernel<128><<<(N_NODES + 7) / 8, 256>>>(x, p_aggX);

    // fork channel 1 (lockstep — measured best schedule)
    cudaEventRecord(evF, 0);
    cudaStreamWaitEvent(s2, evF, 0);

    dim3 ggrid((N_NODES + 127) / 128, 2);
    const int AGRID = (N_NODES + 7) / 8;       // 8 nodes per block (fp16 agg)
    const int LGRID = (N_NODES + 63) / 64;     // gemm_ln grid

    // channel 1 chain (stream s2)
    gemm_tf32<128><<<ggrid, 256, 0, s2>>>(p_aggX, W0 + (size_t)1 * 128 * 256, b0 + 256, p_h2);
    aggregate_h<<<AGRID, 256, 0, s2>>>(p_h2, p_agg2);
    gemm_tf32<256><<<ggrid, 256, 0, s2>>>(p_agg2, W1 + (size_t)1 * 256 * 256, b1 + 256, p_h2);
    aggregate_h<<<AGRID, 256, 0, s2>>>(p_h2, p_agg2);
    gemm_ln<<<LGRID, 256, GL_SMEM_BYTES, s2>>>(p_agg2, W2 + (size_t)1 * 256 * 256, b2 + 256,
                                               lnw, lnb, out + (size_t)1 * N_NODES * 256);
    cudaEventRecord(evJ, s2);

    // channel 0 chain (default stream)
    gemm_tf32<128><<<ggrid, 256>>>(p_aggX, W0, b0, p_h);
    aggregate_h<<<AGRID, 256>>>(p_h, p_agg);
    gemm_tf32<256><<<ggrid, 256>>>(p_agg, W1, b1, p_h);
    aggregate_h<<<AGRID, 256>>>(p_h, p_agg);
    gemm_ln<<<LGRID, 256, GL_SMEM_BYTES>>>(p_agg, W2, b2, lnw, lnb, out);

    // join
    cudaStreamWaitEvent(0, evJ, 0);
}

// round 15
// speedup vs baseline: 1.4023x; 1.4023x over previous
#include <cuda_runtime.h>
#include <cuda_fp16.h>
#include <cuda_bf16.h>

#define N_NODES 50000
#define E_EDGES 800000
#define D_INP   128
#define D_HID   256
#define SCAN_BLOCKS ((N_NODES + 1023) / 1024)   // 49

// ---------------- scratch (device globals; no allocation allowed) ----------------
__device__ __align__(256) float  g_aggX[(size_t)N_NODES * D_INP];   // aggregated x (fp32)
__device__ __align__(256) __half g_h   [(size_t)N_NODES * D_HID];   // ch0 hidden (fp16)
__device__ __align__(256) float  g_agg [(size_t)N_NODES * D_HID];   // ch0 aggregated (fp32)
__device__ __align__(256) __half g_h2  [(size_t)N_NODES * D_HID];   // ch1 hidden (fp16)
__device__ __align__(256) float  g_agg2[(size_t)N_NODES * D_HID];   // ch1 aggregated (fp32)
__device__ __align__(256) int2   g_cw  [E_EDGES];                   // CSR {src, w-bits}
__device__ int   g_cnt[N_NODES];
__device__ int   g_rowptr[N_NODES + 1];
__device__ int   g_pos[N_NODES];
__device__ float g_dinv[N_NODES];
__device__ int   g_blksum[SCAN_BLOCKS];
__device__ int   g_blkoff[SCAN_BLOCKS];
__device__ int   g_mode32;     // 1 = indices are int32, 0 = int64 (read low words)

__device__ __forceinline__ int idx_at(const int* __restrict__ p32, int mode32, int idx) {
    return mode32 ? p32[idx] : p32[2 * (size_t)idx];
}

__device__ __forceinline__ unsigned f2tf(float f) {
    unsigned u;
    asm("cvt.rna.tf32.f32 %0, %1;" : "=r"(u) : "f"(f));
    return u;
}

// ---------------- init: zero counts + dtype detection (block 0) ----------------
__global__ void init_kernel(const int* __restrict__ e32) {
    int i = blockIdx.x * blockDim.x + threadIdx.x;
    if (i < N_NODES) g_cnt[i] = 0;
    if (blockIdx.x == 0) {
        __shared__ int any;
        if (threadIdx.x == 0) any = 0;
        __syncthreads();
        int a = 0;
        #pragma unroll
        for (int s = 0; s < 4; s++) {
            int idx = threadIdx.x * 4 + s;           // 0..1023 samples
            a |= e32[2 * (idx * 391) + 1];           // odd words, within first E ints
        }
        if (a != 0) atomicOr(&any, 1);
        __syncthreads();
        if (threadIdx.x == 0) g_mode32 = any;
    }
}

__global__ void count_kernel(const int* __restrict__ e32) {
    int e = blockIdx.x * blockDim.x + threadIdx.x;
    if (e < E_EDGES) {
        int d = idx_at(e32, g_mode32, E_EDGES + e);
        atomicAdd(&g_cnt[d], 1);
    }
}

// ---------------- hierarchical scan ----------------
__global__ void scanA_kernel() {        // grid=SCAN_BLOCKS, block=1024
    __shared__ int wsum[32];
    int t = threadIdx.x, lane = t & 31, w = t >> 5;
    int idx = blockIdx.x * 1024 + t;
    int v = (idx < N_NODES) ? g_cnt[idx] : 0;
    if (idx < N_NODES) g_dinv[idx] = rsqrtf((float)(v + 1));   // +1 self-loop
    int inc = v;
    #pragma unroll
    for (int d = 1; d < 32; d <<= 1) {
        int n = __shfl_up_sync(0xffffffffu, inc, d);
        if (lane >= d) inc += n;
    }
    if (lane == 31) wsum[w] = inc;
    __syncthreads();
    if (w == 0) {
        int s = wsum[lane];
        #pragma unroll
        for (int d = 1; d < 32; d <<= 1) {
            int n = __shfl_up_sync(0xffffffffu, s, d);
            if (lane >= d) s += n;
        }
        wsum[lane] = s;
    }
    __syncthreads();
    int wbase = (w == 0) ? 0 : wsum[w - 1];
    if (idx < N_NODES) g_rowptr[idx] = wbase + inc - v;   // block-local exclusive
    if (t == 1023) g_blksum[blockIdx.x] = wbase + inc;
}

__global__ void scanB_kernel() {        // 1 block, 64 threads
    int t = threadIdx.x;
    int v = (t < SCAN_BLOCKS) ? g_blksum[t] : 0;
    __shared__ int sh[64];
    sh[t] = v;
    __syncthreads();
    #pragma unroll
    for (int d = 1; d < 64; d <<= 1) {
        int add = (t >= d) ? sh[t - d] : 0;
        __syncthreads();
        sh[t] += add;
        __syncthreads();
    }
    if (t < SCAN_BLOCKS) g_blkoff[t] = sh[t] - v;         // exclusive
    if (t == 0) g_rowptr[N_NODES] = sh[SCAN_BLOCKS - 1];
}

__global__ void scanC_kernel() {
    int i = blockIdx.x * blockDim.x + threadIdx.x;
    if (i < N_NODES) {
        int r = g_rowptr[i] + g_blkoff[i >> 10];
        g_rowptr[i] = r;
        g_pos[i]    = r;
    }
}

__global__ void fill_kernel(const int* __restrict__ e32) {
    int e = blockIdx.x * blockDim.x + threadIdx.x;
    if (e < E_EDGES) {
        int m = g_mode32;
        int s = idx_at(e32, m, e);
        int d = idx_at(e32, m, E_EDGES + e);
        int p = atomicAdd(&g_pos[d], 1);
        g_cw[p] = make_int2(s, __float_as_int(g_dinv[s] * g_dinv[d]));
    }
}

// ---------------- fp32 aggregation for x (layer 0): 8 nodes per 256-thread block ---------
template <int D>
__global__ void aggregate_kernel(const float* __restrict__ h, float* __restrict__ out) {
    const int TPN = D / 4;                     // threads per node (float4 each)
    const int NPB = 256 / TPN;                 // nodes per block
    int v = blockIdx.x * NPB + threadIdx.x / TPN;
    int t = threadIdx.x % TPN;
    if (v >= N_NODES) return;
    const float4* h4 = (const float4*)h;
    float dv = g_dinv[v];
    float sw = dv * dv;
    float4 hv = h4[(size_t)v * TPN + t];
    float4 acc = make_float4(sw * hv.x, sw * hv.y, sw * hv.z, sw * hv.w);
    int beg = g_rowptr[v];
    int end = g_rowptr[v + 1];
    int j = beg;
    for (; j + 8 <= end; j += 8) {            // 8 gathers in flight
        int2 cw[8];
        #pragma unroll
        for (int u = 0; u < 8; u++) cw[u] = __ldg(&g_cw[j + u]);
        float4 hh[8];
        #pragma unroll
        for (int u = 0; u < 8; u++) hh[u] = h4[(size_t)cw[u].x * TPN + t];
        #pragma unroll
        for (int u = 0; u < 8; u++) {
            float wj = __int_as_float(cw[u].y);
            acc.x += wj * hh[u].x;
            acc.y += wj * hh[u].y;
            acc.z += wj * hh[u].z;
            acc.w += wj * hh[u].w;
        }
    }
    for (; j < end; ++j) {
        int2 cw = __ldg(&g_cw[j]);
        float wj = __int_as_float(cw.y);
        float4 hc = h4[(size_t)cw.x * TPN + t];
        acc.x += wj * hc.x;
        acc.y += wj * hc.y;
        acc.z += wj * hc.z;
        acc.w += wj * hc.w;
    }
    ((float4*)out)[(size_t)v * TPN + t] = acc;
}

// ---------------- fp16-input aggregation (D=256): 32 threads/node, 8 halves/thread -------
__device__ __forceinline__ void h8_to_f8(const uint4& u, float* f) {
    float2 a = __half22float2(*(const __half2*)&u.x);
    float2 b = __half22float2(*(const __half2*)&u.y);
    float2 c = __half22float2(*(const __half2*)&u.z);
    float2 d = __half22float2(*(const __half2*)&u.w);
    f[0] = a.x; f[1] = a.y; f[2] = b.x; f[3] = b.y;
    f[4] = c.x; f[5] = c.y; f[6] = d.x; f[7] = d.y;
}

__global__ void aggregate_h(const __half* __restrict__ h, float* __restrict__ out) {
    int v = blockIdx.x * 8 + (threadIdx.x >> 5);   // 8 nodes per 256-thread block
    int t = threadIdx.x & 31;                      // 32 threads per node
    if (v >= N_NODES) return;
    const uint4* h4 = (const uint4*)h;             // 16B = 8 halves
    float dv = g_dinv[v];
    float sw = dv * dv;
    float acc[8], f[8];
    uint4 hv = h4[(size_t)v * 32 + t];
    h8_to_f8(hv, f);
    #pragma unroll
    for (int k = 0; k < 8; k++) acc[k] = sw * f[k];
    int beg = g_rowptr[v];
    int end = g_rowptr[v + 1];
    int j = beg;
    for (; j + 8 <= end; j += 8) {                 // 8 gathers in flight
        int2 cw[8];
        #pragma unroll
        for (int u = 0; u < 8; u++) cw[u] = __ldg(&g_cw[j + u]);
        uint4 hh[8];
        #pragma unroll
        for (int u = 0; u < 8; u++) hh[u] = h4[(size_t)cw[u].x * 32 + t];
        #pragma unroll
        for (int u = 0; u < 8; u++) {
            float wj = __int_as_float(cw[u].y);
            h8_to_f8(hh[u], f);
            #pragma unroll
            for (int k = 0; k < 8; k++) acc[k] += wj * f[k];
        }
    }
    for (; j < end; ++j) {
        int2 cw = __ldg(&g_cw[j]);
        float wj = __int_as_float(cw.y);
        uint4 hc = h4[(size_t)cw.x * 32 + t];
        h8_to_f8(hc, f);
        #pragma unroll
        for (int k = 0; k < 8; k++) acc[k] += wj * f[k];
    }
    float4* o4 = (float4*)out;
    o4[(size_t)v * 64 + t * 2 + 0] = make_float4(acc[0], acc[1], acc[2], acc[3]);
    o4[(size_t)v * 64 + t * 2 + 1] = make_float4(acc[4], acc[5], acc[6], acc[7]);
}

// ---------------- tf32 GEMM + bias + (relu(t)+t) epilogue, fp16 output ----------------
// C[N,256] = A[N,K] @ W[K,256]; BM=128 BN=128 BK=32, 8 warps (R8-proven body)
template <int K>
__launch_bounds__(256)
__global__ void gemm_tf32(const float* __restrict__ A, const float* __restrict__ W,
                          const float* __restrict__ bias, __half* __restrict__ C) {
    __shared__ __align__(16) unsigned As[8 * 128 * 4];   // [chunk][row^chunk][k%4]
    __shared__ __align__(16) unsigned Bs[32 * 136];      // [k][n] stride 136

    const int tid  = threadIdx.x;
    const int lane = tid & 31, wid = tid >> 5;
    const int g  = lane >> 2, t4 = lane & 3;
    const int m0 = blockIdx.x * 128, n0 = blockIdx.y * 128;
    const int wr = (wid & 3) * 32;
    const int wc = (wid >> 2) * 64;

    float acc[2][8][4];
    #pragma unroll
    for (int mt = 0; mt < 2; mt++)
        #pragma unroll
        for (int nt = 0; nt < 8; nt++)
            #pragma unroll
            for (int r = 0; r < 4; r++) acc[mt][nt][r] = 0.f;

    const int la_row = tid >> 3;
    const int la_ch  = tid & 7;
    const int lb_k   = tid >> 5;
    const int lb_n   = (tid & 31) * 4;

    float4 aR[4], bR[4];
    auto fetch = [&](int k0) {
        #pragma unroll
        for (int i = 0; i < 4; i++) {
            int m = m0 + la_row + i * 32;
            aR[i] = (m < N_NODES)
                  ? *(const float4*)&A[(size_t)m * K + k0 + la_ch * 4]
                  : make_float4(0.f, 0.f, 0.f, 0.f);
        }
        #pragma unroll
        for (int i = 0; i < 4; i++) {
            int k = k0 + lb_k + i * 8;
            bR[i] = *(const float4*)&W[(size_t)k * 256 + n0 + lb_n];
        }
    };

    fetch(0);
    for (int k0 = 0; k0 < K; k0 += 32) {
        #pragma unroll
        for (int i = 0; i < 4; i++) {
            uint4 v = make_uint4(f2tf(aR[i].x), f2tf(aR[i].y), f2tf(aR[i].z), f2tf(aR[i].w));
            int row = la_row + i * 32;
            *(uint4*)&As[(la_ch * 128 + (row ^ la_ch)) * 4] = v;
        }
        #pragma unroll
        for (int i = 0; i < 4; i++) {
            uint4 v = make_uint4(f2tf(bR[i].x), f2tf(bR[i].y), f2tf(bR[i].z), f2tf(bR[i].w));
            *(uint4*)&Bs[(lb_k + i * 8) * 136 + lb_n] = v;
        }
        __syncthreads();
        if (k0 + 32 < K) fetch(k0 + 32);

        #pragma unroll
        for (int kk = 0; kk < 4; kk++) {
            const int c0 = 2 * kk, c1 = 2 * kk + 1;
            unsigned a[2][4];
            #pragma unroll
            for (int mt = 0; mt < 2; mt++) {
                int m = wr + mt * 16 + g;
                a[mt][0] = As[(c0 * 128 + (m ^ c0)) * 4 + t4];
                a[mt][1] = As[(c0 * 128 + ((m + 8) ^ c0)) * 4 + t4];
                a[mt][2] = As[(c1 * 128 + (m ^ c1)) * 4 + t4];
                a[mt][3] = As[(c1 * 128 + ((m + 8) ^ c1)) * 4 + t4];
            }
            #pragma unroll
            for (int nt = 0; nt < 8; nt++) {
                int n = wc + nt * 8 + g;
                unsigned b0 = Bs[(kk * 8 + t4) * 136 + n];
                unsigned b1 = Bs[(kk * 8 + t4 + 4) * 136 + n];
                #pragma unroll
                for (int mt = 0; mt < 2; mt++) {
                    asm volatile(
                        "mma.sync.aligned.m16n8k8.row.col.f32.tf32.tf32.f32 "
                        "{%0,%1,%2,%3}, {%4,%5,%6,%7}, {%8,%9}, {%0,%1,%2,%3};"
                        : "+f"(acc[mt][nt][0]), "+f"(acc[mt][nt][1]),
                          "+f"(acc[mt][nt][2]), "+f"(acc[mt][nt][3])
                        : "r"(a[mt][0]), "r"(a[mt][1]), "r"(a[mt][2]), "r"(a[mt][3]),
                          "r"(b0), "r"(b1));
                }
            }
        }
        __syncthreads();
    }

    #pragma unroll
    for (int mt = 0; mt < 2; mt++) {
        int r0 = m0 + wr + mt * 16 + g;
        #pragma unroll
        for (int nt = 0; nt < 8; nt++) {
            int n = n0 + wc + nt * 8 + 2 * t4;
            float bA = bias[n], bB = bias[n + 1];
            if (r0 < N_NODES) {
                float tx = acc[mt][nt][0] + bA;
                float ty = acc[mt][nt][1] + bB;
                *(__half2*)&C[(size_t)r0 * 256 + n] =
                    __floats2half2_rn(fmaxf(tx, 0.f) + tx, fmaxf(ty, 0.f) + ty);
            }
            int r1 = r0 + 8;
            if (r1 < N_NODES) {
                float tx = acc[mt][nt][2] + bA;
                float ty = acc[mt][nt][3] + bB;
                *(__half2*)&C[(size_t)r1 * 256 + n] =
                    __floats2half2_rn(fmaxf(tx, 0.f) + tx, fmaxf(ty, 0.f) + ty);
            }
        }
    }
}

// ---------------- last-layer GEMM with fused LayerNorm (BM=64, BN=256, K=256) ----------
#define GL_AS_WORDS (64 * 64 * 4)
#define GL_BS_WORDS (16 * 260)
#define GL_SMEM_BYTES ((GL_AS_WORDS + GL_BS_WORDS) * 4)

__launch_bounds__(256, 2)
__global__ void gemm_ln(const float* __restrict__ A, const float* __restrict__ W,
                        const float* __restrict__ bias,
                        const float* __restrict__ lnw, const float* __restrict__ lnb,
                        float* __restrict__ C) {
    extern __shared__ __align__(16) unsigned smem[];
    unsigned* As = smem;                       // [row(64)][chunk ^ (row&7)(64)][4]
    unsigned* Bs = smem + GL_AS_WORDS;         // [k(16)][n] stride 260
    float*    Sln = (float*)smem;              // LN scratch (reuses As region, 64KB)

    const int tid  = threadIdx.x;
    const int lane = tid & 31, wid = tid >> 5;
    const int g = lane >> 2, t4 = lane & 3;
    const int m0 = blockIdx.x * 64;
    const int wr = (wid >> 2) * 32;            // 2 row groups
    const int wc = (wid & 3) * 64;             // 4 col groups

    // ---- stage A: load 64x256 A tile into swizzled SMEM ----
    #pragma unroll
    for (int it = 0; it < 16; ++it) {
        int idx = it * 256 + tid;
        int row = idx >> 6;                    // 0..63
        int ch  = idx & 63;                    // k/4 chunk
        int m = m0 + row;
        float4 av = (m < N_NODES)
                  ? *(const float4*)&A[(size_t)m * 256 + ch * 4]
                  : make_float4(0.f, 0.f, 0.f, 0.f);
        uint4 tv = make_uint4(f2tf(av.x), f2tf(av.y), f2tf(av.z), f2tf(av.w));
        *(uint4*)&As[(row * 64 + (ch ^ (row & 7))) * 4] = tv;
    }
    __syncthreads();

    // ---- stage B: GEMM over K=256 in 16-k slabs ----
    float acc[2][8][4];
    #pragma unroll
    for (int mt = 0; mt < 2; mt++)
        #pragma unroll
        for (int nt = 0; nt < 8; nt++)
            #pragma unroll
            for (int r = 0; r < 4; r++) acc[mt][nt][r] = 0.f;

    const int lb_k = tid >> 6;                 // 0..3 (+i*4 -> rows 0..15)
    const int lb_n = (tid & 63) * 4;           // full 256 cols
    float4 bR[4];
    auto fetchW = [&](int k0) {
        #pragma unroll
        for (int i = 0; i < 4; i++)
            bR[i] = *(const float4*)&W[(size_t)(k0 + lb_k + i * 4) * 256 + lb_n];
    };

    fetchW(0);
    for (int k0 = 0; k0 < 256; k0 += 16) {
        #pragma unroll
        for (int i = 0; i < 4; i++) {
            uint4 v = make_uint4(f2tf(bR[i].x), f2tf(bR[i].y), f2tf(bR[i].z), f2tf(bR[i].w));
            *(uint4*)&Bs[(lb_k + i * 4) * 260 + lb_n] = v;
        }
        __syncthreads();
        if (k0 + 16 < 256) fetchW(k0 + 16);

        const int cb = k0 >> 2;
        #pragma unroll
        for (int kk = 0; kk < 2; kk++) {
            const int c0 = cb + 2 * kk, c1 = c0 + 1;
            unsigned a[2][4];
            #pragma unroll
            for (int mt = 0; mt < 2; mt++) {
                int m = wr + mt * 16 + g;      // m&7 == g
                a[mt][0] = As[(m * 64 + (c0 ^ g)) * 4 + t4];
                a[mt][1] = As[((m + 8) * 64 + (c0 ^ g)) * 4 + t4];
                a[mt][2] = As[(m * 64 + (c1 ^ g)) * 4 + t4];
                a[mt][3] = As[((m + 8) * 64 + (c1 ^ g)) * 4 + t4];
            }
            #pragma unroll
            for (int nt = 0; nt < 8; nt++) {
                int n = wc + nt * 8 + g;
                unsigned b0 = Bs[(kk * 8 + t4) * 260 + n];
                unsigned b1 = Bs[(kk * 8 + t4 + 4) * 260 + n];
                #pragma unroll
                for (int mt = 0; mt < 2; mt++) {
                    asm volatile(
                        "mma.sync.aligned.m16n8k8.row.col.f32.tf32.tf32.f32 "
                        "{%0,%1,%2,%3}, {%4,%5,%6,%7}, {%8,%9}, {%0,%1,%2,%3};"
                        : "+f"(acc[mt][nt][0]), "+f"(acc[mt][nt][1]),
                          "+f"(acc[mt][nt][2]), "+f"(acc[mt][nt][3])
                        : "r"(a[mt][0]), "r"(a[mt][1]), "r"(a[mt][2]), "r"(a[mt][3]),
                          "r"(b0), "r"(b1));
                }
            }
        }
        __syncthreads();
    }

    // ---- stage C: bias + relu-residual -> Sln, then LayerNorm -> C ----
    #pragma unroll
    for (int mt = 0; mt < 2; mt++) {
        int lr = wr + mt * 16 + g;
        #pragma unroll
        for (int nt = 0; nt < 8; nt++) {
            int n = wc + nt * 8 + 2 * t4;
            float bA = bias[n], bB = bias[n + 1];
            float tx = acc[mt][nt][0] + bA;
            float ty = acc[mt][nt][1] + bB;
            *(float2*)&Sln[lr * 256 + n] =
                make_float2(fmaxf(tx, 0.f) + tx, fmaxf(ty, 0.f) + ty);
            tx = acc[mt][nt][2] + bA;
            ty = acc[mt][nt][3] + bB;
            *(float2*)&Sln[(lr + 8) * 256 + n] =
                make_float2(fmaxf(tx, 0.f) + tx, fmaxf(ty, 0.f) + ty);
        }
    }
    __syncthreads();
    const float4* lnw4 = (const float4*)lnw;
    const float4* lnb4 = (const float4*)lnb;
    #pragma unroll 1
    for (int r = 0; r < 8; r++) {
        int row = wid * 8 + r;
        int v = m0 + row;
        if (v >= N_NODES) break;
        float4 a = ((const float4*)&Sln[row * 256])[lane];
        float4 b = ((const float4*)&Sln[row * 256])[lane + 32];
        float s1 = a.x + a.y + a.z + a.w + b.x + b.y + b.z + b.w;
        float s2 = a.x*a.x + a.y*a.y + a.z*a.z + a.w*a.w
                 + b.x*b.x + b.y*b.y + b.z*b.z + b.w*b.w;
        #pragma unroll
        for (int off = 16; off > 0; off >>= 1) {
            s1 += __shfl_xor_sync(0xffffffffu, s1, off);
            s2 += __shfl_xor_sync(0xffffffffu, s2, off);
        }
        float mean = s1 * (1.f / 256.f);
        float var  = s2 * (1.f / 256.f) - mean * mean;
        float rs = rsqrtf(var + 1e-6f);
        float4 w1 = lnw4[lane], w2 = lnw4[lane + 32];
        float4 z1 = lnb4[lane], z2 = lnb4[lane + 32];
        float4 o1 = make_float4((a.x - mean) * rs * w1.x + z1.x,
                                (a.y - mean) * rs * w1.y + z1.y,
                                (a.z - mean) * rs * w1.z + z1.z,
                                (a.w - mean) * rs * w1.w + z1.w);
        float4 o2 = make_float4((b.x - mean) * rs * w2.x + z2.x,
                                (b.y - mean) * rs * w2.y + z2.y,
                                (b.z - mean) * rs * w2.z + z2.z,
                                (b.w - mean) * rs * w2.w + z2.w);
        ((float4*)&C[(size_t)v * 256])[lane]      = o1;
        ((float4*)&C[(size_t)v * 256])[lane + 32] = o2;
    }
}

__global__ void batchs_kernel(const int* __restrict__ b32, float* __restrict__ out) {
    int i = blockIdx.x * blockDim.x + threadIdx.x;
    if (i < N_NODES) {
        float bv = (float)idx_at(b32, g_mode32, i);
        out[i]           = bv;   // channel 0
        out[N_NODES + i] = bv;   // channel 1
    }
}

// ---------------- launcher (R8-proven schedule: batchs hoist + lockstep fork) ----------
extern "C" void kernel_launch(void* const* d_in, const int* in_sizes, int n_in,
                              void* d_out, int out_size) {
    const float* x    = (const float*)d_in[0];
    const int*   e32  = (const int*)d_in[1];
    const int*   b32  = (const int*)d_in[2];
    const float* W0 = (const float*)d_in[3];
    const float* b0 = (const float*)d_in[4];
    const float* W1 = (const float*)d_in[5];
    const float* b1 = (const float*)d_in[6];
    const float* W2 = (const float*)d_in[7];
    const float* b2 = (const float*)d_in[8];
    const float* lnw = (const float*)d_in[9];
    const float* lnb = (const float*)d_in[10];
    float* out = (float*)d_out;

    float *p_aggX, *p_agg, *p_agg2;
    __half *p_h, *p_h2;
    cudaGetSymbolAddress((void**)&p_aggX, g_aggX);
    cudaGetSymbolAddress((void**)&p_h,    g_h);
    cudaGetSymbolAddress((void**)&p_agg,  g_agg);
    cudaGetSymbolAddress((void**)&p_h2,   g_h2);
    cudaGetSymbolAddress((void**)&p_agg2, g_agg2);

    static cudaStream_t s2 = nullptr;
    static cudaEvent_t evI = nullptr, evF = nullptr, evJ = nullptr;
    if (!s2) {
        cudaStreamCreateWithFlags(&s2, cudaStreamNonBlocking);
        cudaEventCreateWithFlags(&evI, cudaEventDisableTiming);
        cudaEventCreateWithFlags(&evF, cudaEventDisableTiming);
        cudaEventCreateWithFlags(&evJ, cudaEventDisableTiming);
        cudaFuncSetAttribute(gemm_ln,
                             cudaFuncAttributeMaxDynamicSharedMemorySize, GL_SMEM_BYTES);
    }

    const int TB = 256;
    init_kernel <<<(N_NODES + TB - 1) / TB, TB>>>(e32);
    cudaEventRecord(evI, 0);                    // g_mode32 ready
    cudaStreamWaitEvent(s2, evI, 0);
    batchs_kernel<<<(N_NODES + TB - 1) / TB, TB, 0, s2>>>(b32, out + (size_t)2 * N_NODES * 256);

    count_kernel<<<(E_EDGES + TB - 1) / TB, TB>>>(e32);
    scanA_kernel<<<SCAN_BLOCKS, 1024>>>();
    scanB_kernel<<<1, 64>>>();
    scanC_kernel<<<(N_NODES + TB - 1) / TB, TB>>>();
    fill_kernel <<<(E_EDGES + TB - 1) / TB, TB>>>(e32);

    // shared layer-0 aggregation of x (128-dim, fp32): 8 nodes per 256-thread block
    aggregate_kernel<128><<<(N_NODES + 7) / 8, 256>>>(x, p_aggX);

    // fork channel 1 (lockstep — measured best schedule)
    cudaEventRecord(evF, 0);
    cudaStreamWaitEvent(s2, evF, 0);

    dim3 ggrid((N_NODES + 127) / 128, 2);
    const int AGRID = (N_NODES + 7) / 8;       // 8 nodes per block (fp16 agg)
    const int LGRID = (N_NODES + 63) / 64;     // gemm_ln grid

    // channel 1 chain (stream s2)
    gemm_tf32<128><<<ggrid, 256, 0, s2>>>(p_aggX, W0 + (size_t)1 * 128 * 256, b0 + 256, p_h2);
    aggregate_h<<<AGRID, 256, 0, s2>>>(p_h2, p_agg2);
    gemm_tf32<256><<<ggrid, 256, 0, s2>>>(p_agg2, W1 + (size_t)1 * 256 * 256, b1 + 256, p_h2);
    aggregate_h<<<AGRID, 256, 0, s2>>>(p_h2, p_agg2);
    gemm_ln<<<LGRID, 256, GL_SMEM_BYTES, s2>>>(p_agg2, W2 + (size_t)1 * 256 * 256, b2 + 256,
                                               lnw, lnb, out + (size_t)1 * N_NODES * 256);
    cudaEventRecord(evJ, s2);

    // channel 0 chain (default stream)
    gemm_tf32<128><<<ggrid, 256>>>(p_aggX, W0, b0, p_h);
    aggregate_h<<<AGRID, 256>>>(p_h, p_agg);
    gemm_tf32<256><<<ggrid, 256>>>(p_agg, W1, b1, p_h);
    aggregate_h<<<AGRID, 256>>>(p_h, p_agg);
    gemm_ln<<<LGRID, 256, GL_SMEM_BYTES>>>(p_agg, W2, b2, lnw, lnb, out);

    // join
    cudaStreamWaitEvent(0, evJ, 0);
}